// round 1
// baseline (speedup 1.0000x reference)
#include <cuda_runtime.h>
#include <math.h>

#define BSZ   2
#define NN    512
#define DIN   256
#define HEADS 8
#define DOUT  64
#define HD    512        // HEADS*DOUT
#define ROWS  1024       // BSZ*NN
#define ALPHA 0.2f

// Scratch (device globals: no allocation allowed in kernel_launch)
__device__ float g_src [ROWS * HD];
__device__ float g_tgt [ROWS * HD];
__device__ float g_skip[ROWS * HD];
__device__ float g_asrc[BSZ * HEADS * NN];   // [b][h][n]  = s_h . src
__device__ float g_atgt[BSZ * HEADS * NN];   // [b][h][m]  = s_h . tgt

// ---------------------------------------------------------------------------
// K1: three projections C = X @ W  (X:[1024,256], W:[256,512])
// 64x64 tile, 16 k-slab, 4x4 register micro-tile, 256 threads
// ---------------------------------------------------------------------------
__global__ void __launch_bounds__(256) gemm3_kernel(
    const float* __restrict__ X,
    const float* __restrict__ Wsrc,
    const float* __restrict__ Wtgt,
    const float* __restrict__ Wskip)
{
    const float* W = (blockIdx.z == 0) ? Wsrc : (blockIdx.z == 1) ? Wtgt : Wskip;
    float* C = (blockIdx.z == 0) ? g_src : (blockIdx.z == 1) ? g_tgt : g_skip;

    const int rowBase = blockIdx.y * 64;
    const int colBase = blockIdx.x * 64;

    __shared__ __align__(16) float As[16][72];   // pad 72: 4-way STS conflict max
    __shared__ __align__(16) float Bs[16][64];

    const int t  = threadIdx.x;
    const int ty = t >> 4, tx = t & 15;
    const int ak = t & 15, ar = t >> 4;   // A loader
    const int bc = t & 63, bk = t >> 6;   // B loader

    float acc[4][4];
#pragma unroll
    for (int i = 0; i < 4; i++)
#pragma unroll
        for (int j = 0; j < 4; j++) acc[i][j] = 0.f;

    for (int k0 = 0; k0 < DIN; k0 += 16) {
#pragma unroll
        for (int i = 0; i < 4; i++)
            As[ak][ar + 16 * i] = X[(size_t)(rowBase + ar + 16 * i) * DIN + k0 + ak];
#pragma unroll
        for (int i = 0; i < 4; i++)
            Bs[bk + 4 * i][bc] = W[(size_t)(k0 + bk + 4 * i) * HD + colBase + bc];
        __syncthreads();

#pragma unroll
        for (int kk = 0; kk < 16; kk++) {
            float4 a = *(const float4*)&As[kk][ty * 4];
            float4 b = *(const float4*)&Bs[kk][tx * 4];
            acc[0][0] = fmaf(a.x, b.x, acc[0][0]); acc[0][1] = fmaf(a.x, b.y, acc[0][1]);
            acc[0][2] = fmaf(a.x, b.z, acc[0][2]); acc[0][3] = fmaf(a.x, b.w, acc[0][3]);
            acc[1][0] = fmaf(a.y, b.x, acc[1][0]); acc[1][1] = fmaf(a.y, b.y, acc[1][1]);
            acc[1][2] = fmaf(a.y, b.z, acc[1][2]); acc[1][3] = fmaf(a.y, b.w, acc[1][3]);
            acc[2][0] = fmaf(a.z, b.x, acc[2][0]); acc[2][1] = fmaf(a.z, b.y, acc[2][1]);
            acc[2][2] = fmaf(a.z, b.z, acc[2][2]); acc[2][3] = fmaf(a.z, b.w, acc[2][3]);
            acc[3][0] = fmaf(a.w, b.x, acc[3][0]); acc[3][1] = fmaf(a.w, b.y, acc[3][1]);
            acc[3][2] = fmaf(a.w, b.z, acc[3][2]); acc[3][3] = fmaf(a.w, b.w, acc[3][3]);
        }
        __syncthreads();
    }

#pragma unroll
    for (int i = 0; i < 4; i++) {
        float4 v = make_float4(acc[i][0], acc[i][1], acc[i][2], acc[i][3]);
        *(float4*)&C[(size_t)(rowBase + ty * 4 + i) * HD + colBase + tx * 4] = v;
    }
}

// ---------------------------------------------------------------------------
// K1b: rank-1 terms  a_src[b,h,n] = s_h . src_row,  a_tgt[b,h,n] = s_h . tgt_row
// One block per (b,n) row; warp h handles head h.
// ---------------------------------------------------------------------------
__global__ void __launch_bounds__(256) rank1_kernel(const float* __restrict__ scoring)
{
    const int row  = blockIdx.x;        // 0..1023
    const int t    = threadIdx.x;
    const int h    = t >> 5;
    const int lane = t & 31;
    const int b = row >> 9, n = row & (NN - 1);

    const float s0 = scoring[h * 64 + lane];
    const float s1 = scoring[h * 64 + lane + 32];
    const float* sr = g_src + (size_t)row * HD + h * 64;
    const float* tr = g_tgt + (size_t)row * HD + h * 64;
    float vs = s0 * sr[lane] + s1 * sr[lane + 32];
    float vt = s0 * tr[lane] + s1 * tr[lane + 32];
#pragma unroll
    for (int off = 16; off; off >>= 1) {
        vs += __shfl_xor_sync(0xffffffffu, vs, off);
        vt += __shfl_xor_sync(0xffffffffu, vt, off);
    }
    if (lane == 0) {
        g_asrc[(size_t)(b * HEADS + h) * NN + n] = vs;
        g_atgt[(size_t)(b * HEADS + h) * NN + n] = vt;
    }
}

// ---------------------------------------------------------------------------
// K2: fused scores + mask + softmax + aggregation + skip + bias + ELU
// One block per (8 query rows, head, batch). 256 threads.
// ---------------------------------------------------------------------------
__global__ void __launch_bounds__(256) attn_kernel(
    const int*   __restrict__ adj,
    const float* __restrict__ scoring,
    const float* __restrict__ bias,
    float*       __restrict__ out)
{
    const int t     = threadIdx.x;
    const int nBase = blockIdx.x * 8;
    const int h     = blockIdx.y;
    const int b     = blockIdx.z;
    const int bh    = b * HEADS + h;

    __shared__ __align__(16) float sh_t[64][68];   // tgt / value tile (padded)
    __shared__ float sh_sc[8][512];                // scores -> probs -> combine buf
    __shared__ __align__(16) float sh_src[8][68];  // query src rows
    __shared__ __align__(16) float sh_s[64];       // 0.8 * scoring[h]
    __shared__ float sh_atgt[512];
    __shared__ float sh_asrc[8];
    __shared__ float sh_inv[8];

    // ---- prologue loads ----
    if (t < 16) {
        float4 v = *(const float4*)&scoring[h * 64 + t * 4];
        v.x *= (1.f - ALPHA); v.y *= (1.f - ALPHA);
        v.z *= (1.f - ALPHA); v.w *= (1.f - ALPHA);
        *(float4*)&sh_s[t * 4] = v;
    }
    sh_atgt[t]       = g_atgt[(size_t)bh * NN + t];
    sh_atgt[t + 256] = g_atgt[(size_t)bh * NN + t + 256];
    if (t < 8) sh_asrc[t] = g_asrc[(size_t)bh * NN + nBase + t];
    if (t < 128) {
        int r = t >> 4, c4 = t & 15;
        *(float4*)&sh_src[r][c4 * 4] =
            *(const float4*)&g_src[(size_t)(b * NN + nBase + r) * HD + h * 64 + c4 * 4];
    }
    __syncthreads();

    // ---- phase 1: scores ----
    const int n_loc = t >> 5;
    const int m0    = t & 31;
    const float a_n = sh_asrc[n_loc];
    const float* srow = &sh_src[n_loc][0];
    const size_t adjRow = (size_t)(b * NN + nBase + n_loc) * NN;

    for (int mt = 0; mt < NN; mt += 64) {
#pragma unroll
        for (int i = 0; i < 4; i++) {
            int idx = t + i * 256;
            int r = idx >> 4, c4 = idx & 15;
            *(float4*)&sh_t[r][c4 * 4] =
                *(const float4*)&g_tgt[(size_t)(b * NN + mt + r) * HD + h * 64 + c4 * 4];
        }
        __syncthreads();

        float acc0 = 0.f, acc1 = 0.f;
#pragma unroll
        for (int d4 = 0; d4 < 16; d4++) {
            float4 s4 = *(const float4*)&sh_s[d4 * 4];
            float4 a4 = *(const float4*)&srow[d4 * 4];
            float4 t0 = *(const float4*)&sh_t[m0][d4 * 4];
            float4 t1 = *(const float4*)&sh_t[m0 + 32][d4 * 4];
            acc0 = fmaf(s4.x, fmaxf(a4.x + t0.x, 0.f), acc0);
            acc0 = fmaf(s4.y, fmaxf(a4.y + t0.y, 0.f), acc0);
            acc0 = fmaf(s4.z, fmaxf(a4.z + t0.z, 0.f), acc0);
            acc0 = fmaf(s4.w, fmaxf(a4.w + t0.w, 0.f), acc0);
            acc1 = fmaf(s4.x, fmaxf(a4.x + t1.x, 0.f), acc1);
            acc1 = fmaf(s4.y, fmaxf(a4.y + t1.y, 0.f), acc1);
            acc1 = fmaf(s4.z, fmaxf(a4.z + t1.z, 0.f), acc1);
            acc1 = fmaf(s4.w, fmaxf(a4.w + t1.w, 0.f), acc1);
        }
        const int mg0 = mt + m0, mg1 = mt + m0 + 32;
        float sc0 = fmaf(ALPHA, a_n + sh_atgt[mg0], acc0);
        float sc1 = fmaf(ALPHA, a_n + sh_atgt[mg1], acc1);
        if (adj[adjRow + mg0] == 0) sc0 += -1.0e9f;
        if (adj[adjRow + mg1] == 0) sc1 += -1.0e9f;
        sh_sc[n_loc][mg0] = sc0;
        sh_sc[n_loc][mg1] = sc1;
        __syncthreads();
    }

    // ---- softmax (unnormalized; keep 1/sum) ----
    {
        const int w = t >> 5, lane = t & 31;
        float mx = -3.4e38f;
#pragma unroll
        for (int m = lane; m < NN; m += 32) mx = fmaxf(mx, sh_sc[w][m]);
#pragma unroll
        for (int off = 16; off; off >>= 1)
            mx = fmaxf(mx, __shfl_xor_sync(0xffffffffu, mx, off));
        float sum = 0.f;
#pragma unroll
        for (int m = lane; m < NN; m += 32) {
            float p = __expf(sh_sc[w][m] - mx);
            sh_sc[w][m] = p;
            sum += p;
        }
#pragma unroll
        for (int off = 16; off; off >>= 1)
            sum += __shfl_xor_sync(0xffffffffu, sum, off);
        if (lane == 0) sh_inv[w] = 1.f / sum;
    }
    __syncthreads();

    // ---- phase 2: aggregation (values = src rows) ----
    const int half = t >> 7;             // m-range split
    const int n0   = ((t >> 5) & 3) * 2; // 2 query rows
    const int d0   = (t & 31) * 2;       // 2 feature cols
    float acc00 = 0.f, acc01 = 0.f, acc10 = 0.f, acc11 = 0.f;

    for (int mt = 0; mt < NN; mt += 64) {
#pragma unroll
        for (int i = 0; i < 4; i++) {
            int idx = t + i * 256;
            int r = idx >> 4, c4 = idx & 15;
            *(float4*)&sh_t[r][c4 * 4] =
                *(const float4*)&g_src[(size_t)(b * NN + mt + r) * HD + h * 64 + c4 * 4];
        }
        __syncthreads();

        const int ms = half * 32;
        const float* p0r = &sh_sc[n0][mt + ms];
        const float* p1r = &sh_sc[n0 + 1][mt + ms];
#pragma unroll 8
        for (int mm = 0; mm < 32; mm++) {
            float p0 = p0r[mm], p1 = p1r[mm];
            float2 v = *(const float2*)&sh_t[ms + mm][d0];
            acc00 = fmaf(p0, v.x, acc00);
            acc01 = fmaf(p0, v.y, acc01);
            acc10 = fmaf(p1, v.x, acc10);
            acc11 = fmaf(p1, v.y, acc11);
        }
        __syncthreads();
    }

    // combine the two m-halves via shared (sh_sc free after phase 2)
    if (half == 1) {
        sh_sc[n0][d0]     = acc00; sh_sc[n0][d0 + 1]     = acc01;
        sh_sc[n0 + 1][d0] = acc10; sh_sc[n0 + 1][d0 + 1] = acc11;
    }
    __syncthreads();
    if (half == 0) {
        acc00 += sh_sc[n0][d0];     acc01 += sh_sc[n0][d0 + 1];
        acc10 += sh_sc[n0 + 1][d0]; acc11 += sh_sc[n0 + 1][d0 + 1];
        const float inv0 = sh_inv[n0], inv1 = sh_inv[n0 + 1];
        const int col = h * 64 + d0;
        const size_t r0 = (size_t)(b * NN + nBase + n0) * HD + col;
        const size_t r1 = r0 + HD;
        const float bx = bias[col], by = bias[col + 1];
        float o;
        o = fmaf(acc00, inv0, g_skip[r0]     + bx); out[r0]     = (o > 0.f) ? o : expm1f(o);
        o = fmaf(acc01, inv0, g_skip[r0 + 1] + by); out[r0 + 1] = (o > 0.f) ? o : expm1f(o);
        o = fmaf(acc10, inv1, g_skip[r1]     + bx); out[r1]     = (o > 0.f) ? o : expm1f(o);
        o = fmaf(acc11, inv1, g_skip[r1 + 1] + by); out[r1 + 1] = (o > 0.f) ? o : expm1f(o);
    }
}

// Optional second output: reference returns (out, adj)
__global__ void __launch_bounds__(256) copy_adj_kernel(
    const int* __restrict__ adj, float* __restrict__ dst, int n)
{
    int i = blockIdx.x * 256 + threadIdx.x;
    if (i < n) dst[i] = (float)adj[i];
}

extern "C" void kernel_launch(void* const* d_in, const int* in_sizes, int n_in,
                              void* d_out, int out_size)
{
    const float* x       = (const float*)d_in[0];
    const int*   adj     = (const int*)  d_in[1];
    const float* Wsrc    = (const float*)d_in[2];
    const float* Wtgt    = (const float*)d_in[3];
    const float* Wskip   = (const float*)d_in[4];
    const float* scoring = (const float*)d_in[5];
    const float* bias    = (const float*)d_in[6];
    float* out = (float*)d_out;

    gemm3_kernel<<<dim3(HD / 64, ROWS / 64, 3), 256>>>(x, Wsrc, Wtgt, Wskip);
    rank1_kernel<<<ROWS, 256>>>(scoring);
    attn_kernel<<<dim3(NN / 8, HEADS, BSZ), 256>>>(adj, scoring, bias, out);

    const int main_elems = ROWS * HD;               // 524288
    if (out_size > main_elems) {
        int extra = out_size - main_elems;
        const int adj_elems = BSZ * NN * NN;        // 524288
        if (extra > adj_elems) extra = adj_elems;
        copy_adj_kernel<<<(extra + 255) / 256, 256>>>(adj, out + main_elems, extra);
    }
}